// round 1
// baseline (speedup 1.0000x reference)
#include <cuda_runtime.h>

#define NG  8     // graphs
#define NN  128   // nodes
#define DIM 128   // embedding dim
#define NE  128   // edge types
#define VEC 300   // word-vec dim
#define RPB 8     // edge-rows per block in matrix phase

// ---- scratch (device globals; no allocations allowed) ----
__device__ float g_base[NN][DIM];        // data embeddings per node
__device__ float g_vacc[NG][NN][DIM];    // accumulated child (vector) contributions
__device__ float g_bvec[NG][NN][DIM];    // finalized broadcast vector for path nodes
__device__ int   g_parent[NG][NN];
__device__ int   g_ccount[NG][NN];
__device__ int   g_cdone[NG][NN];
__device__ int   g_onpath[NG][NN];
__device__ int   g_path[NG][NN];
__device__ int   g_plen[NG];
__device__ int   g_edges_eff[NN];
__device__ float g_dscore;
__device__ int   g_taskctr;

// ---------------------------------------------------------------------------
// Init: zero scratch, build tree structure (parents, child counts, pos->root
// path, on-path flags) per graph. One block per graph.
// ---------------------------------------------------------------------------
__global__ void k_init(const int* __restrict__ graphs,
                       const int* __restrict__ edges,
                       const int* __restrict__ posp) {
    int g = blockIdx.x, t = threadIdx.x;
    int pos = posp[0];
    g_ccount[g][t] = 0;
    g_cdone[g][t]  = 0;
    g_onpath[g][t] = 0;
    for (int n = 0; n < NN; ++n) g_vacc[g][n][t] = 0.f;
    if (g == 0) {
        g_edges_eff[t] = (t == pos) ? -1 : edges[t];
        if (t == 0) g_taskctr = 0;
    }
    __syncthreads();
    int off = graphs[g * NN + t];
    int par = (off == 0) ? -1 : (t + off);   // parent index strictly > t
    g_parent[g][t] = par;
    if (par >= 0) atomicAdd(&g_ccount[g][par], 1);
    if (t == 0) {
        int cur = pos, len = 0;
        while (len < NN) {
            g_path[g][len++] = cur;
            g_onpath[g][cur] = 1;
            int o = graphs[g * NN + cur];
            if (o == 0) break;               // reached root
            cur += o;
        }
        g_plen[g] = len;
    }
}

// ---------------------------------------------------------------------------
// Base embeddings: base[n] = data_vecs[data[n]] @ dW + db, plus d_score.
// Blocks 0..127: one node each. Block 128: d_score scalar.
// ---------------------------------------------------------------------------
__global__ void k_base(const int* __restrict__ data,
                       const float* __restrict__ vecs,
                       const float* __restrict__ dW,
                       const float* __restrict__ db,
                       const float* __restrict__ sdw,
                       const float* __restrict__ sbias,
                       const int* __restrict__ posp) {
    int t = threadIdx.x;
    __shared__ float red[DIM];
    if (blockIdx.x < NN) {
        int n = blockIdx.x;
        const float* v = vecs + (long long)data[n] * VEC;
        float acc = db[t];
        #pragma unroll 4
        for (int k = 0; k < VEC; ++k) acc += v[k] * dW[k * DIM + t];
        g_base[n][t] = acc;
    } else {
        int pos = posp[0];
        const float* v = vecs + (long long)data[pos] * VEC;
        float acc = db[t];
        #pragma unroll 4
        for (int k = 0; k < VEC; ++k) acc += v[k] * dW[k * DIM + t];
        red[t] = acc * sdw[t];
        __syncthreads();
        for (int s = 64; s > 0; s >>= 1) {
            if (t < s) red[t] += red[t + s];
            __syncthreads();
        }
        if (t == 0) g_dscore = sbias[0] + red[0];
    }
}

// ---------------------------------------------------------------------------
// Vector phase: persistent task kernel. Task id = n*NG + g (topological:
// children have smaller node index than parents). Each task waits for its
// children via a done-counter, finalizes its vector, and either stores it
// (path nodes — their contribution to the parent is the matrix, handled in
// k_matrix) or transforms it (128x128 matvec) and atomically adds to parent.
// Grid must be <= SM count so all blocks are co-resident (spin safety).
// ---------------------------------------------------------------------------
__global__ void k_vector(const float* __restrict__ ew,
                         const float* __restrict__ ebias) {
    __shared__ float sh_r[DIM];
    __shared__ int sh_task;
    int t = threadIdx.x;
    while (true) {
        if (t == 0) sh_task = atomicAdd(&g_taskctr, 1);
        __syncthreads();
        int task = sh_task;
        if (task >= NG * NN) return;
        int n = task / NG;
        int g = task - n * NG;
        int need = g_ccount[g][n];
        if (t == 0) {
            volatile int* cd = &g_cdone[g][n];
            while (*cd < need) { }
        }
        __syncthreads();
        __threadfence();
        float v = g_base[n][t] + g_vacc[g][n][t];
        int par = g_parent[g][n];
        if (g_onpath[g][n]) {
            g_bvec[g][n][t] = v;             // raw; relu applied in matrix phase
            __threadfence();
            __syncthreads();
            if (t == 0 && par >= 0) atomicAdd(&g_cdone[g][par], 1);
        } else {
            float r = (need > 0) ? fmaxf(v, 0.f) : v;   // relu only if internal
            sh_r[t] = r;
            __syncthreads();
            int eid = g_edges_eff[n];        // n != pos here, so eid >= 0
            const float* W = ew + eid * DIM * DIM;
            float acc = ebias[eid * DIM + t];
            #pragma unroll 8
            for (int k = 0; k < DIM; ++k) acc += sh_r[k] * W[k * DIM + t];
            atomicAdd(&g_vacc[g][par][t], acc);
            __threadfence();
            __syncthreads();
            if (t == 0) atomicAdd(&g_cdone[g][par], 1);
        }
        __syncthreads();                     // protect sh_task / sh_r reuse
    }
}

// ---------------------------------------------------------------------------
// Matrix phase: each edge-type row e is an independent chain of matvecs
// along the pos->root path. Block = (graph, 8 consecutive rows).
//   step 0: m_e = relu?(v[pos]) @ W[e] + b[e]            (per-row weights)
//   step k: m_e = relu(bvec[a_k] + m_e) @ W[edges[a_k]] + b
//   score  = d_score + m_e . sew
// ---------------------------------------------------------------------------
__global__ void k_matrix(const float* __restrict__ ew,
                         const float* __restrict__ ebias,
                         const float* __restrict__ sew,
                         float* __restrict__ out) {
    __shared__ float sh_r[RPB][DIM];
    __shared__ float red[DIM];
    int t  = threadIdx.x;
    int g  = blockIdx.x / (NE / RPB);
    int eb = blockIdx.x % (NE / RPB);
    int e0 = eb * RPB;
    int plen = g_plen[g];
    int p0 = g_path[g][0];
    float m[RPB];

    // step 0: all rows share the same input vector, distinct weights W[e]
    {
        float v = g_bvec[g][p0][t];
        float r0 = (g_ccount[g][p0] > 0) ? fmaxf(v, 0.f) : v;
        sh_r[0][t] = r0;
        __syncthreads();
        #pragma unroll
        for (int row = 0; row < RPB; ++row) {
            int e = e0 + row;
            const float* W = ew + e * DIM * DIM;
            float acc = ebias[e * DIM + t];
            #pragma unroll 8
            for (int k = 0; k < DIM; ++k) acc += sh_r[0][k] * W[k * DIM + t];
            m[row] = acc;
        }
        __syncthreads();
    }

    // steps 1..plen-1: shared weight matrix per graph-step
    for (int s = 1; s < plen; ++s) {
        int a = g_path[g][s];
        float bv = g_bvec[g][a][t];
        #pragma unroll
        for (int row = 0; row < RPB; ++row)
            sh_r[row][t] = fmaxf(bv + m[row], 0.f);   // path nodes always internal
        __syncthreads();
        int eid = g_edges_eff[a];
        const float* W = ew + eid * DIM * DIM;
        float bb = ebias[eid * DIM + t];
        #pragma unroll
        for (int row = 0; row < RPB; ++row) m[row] = bb;
        #pragma unroll 4
        for (int k = 0; k < DIM; ++k) {
            float w = W[k * DIM + t];
            #pragma unroll
            for (int row = 0; row < RPB; ++row)
                m[row] += sh_r[row][k] * w;
        }
        __syncthreads();
    }

    // score: d_score + m . sew (per row)
    float sw = sew[t];
    float ds = g_dscore;
    for (int row = 0; row < RPB; ++row) {
        red[t] = m[row] * sw;
        __syncthreads();
        for (int s = 64; s > 0; s >>= 1) {
            if (t < s) red[t] += red[t + s];
            __syncthreads();
        }
        if (t == 0) out[g * NE + e0 + row] = ds + red[0];
        __syncthreads();
    }
}

extern "C" void kernel_launch(void* const* d_in, const int* in_sizes, int n_in,
                              void* d_out, int out_size) {
    const int*   data   = (const int*)d_in[0];
    // d_in[1] = types (unused: single data_type)
    const int*   graphs = (const int*)d_in[2];
    const int*   edges  = (const int*)d_in[3];
    const int*   posp   = (const int*)d_in[4];
    const float* vecs   = (const float*)d_in[5];
    const float* dW     = (const float*)d_in[6];
    const float* db     = (const float*)d_in[7];
    const float* ew     = (const float*)d_in[8];
    const float* ebias  = (const float*)d_in[9];
    const float* sew    = (const float*)d_in[10];
    const float* sdw    = (const float*)d_in[11];
    const float* sbias  = (const float*)d_in[12];
    float* out = (float*)d_out;

    k_init<<<NG, NN>>>(graphs, edges, posp);
    k_base<<<NN + 1, DIM>>>(data, vecs, dW, db, sdw, sbias, posp);
    k_vector<<<128, DIM>>>(ew, ebias);
    k_matrix<<<NG * (NE / RPB), DIM>>>(ew, ebias, sew, out);
}